// round 11
// baseline (speedup 1.0000x reference)
#include <cuda_runtime.h>
#include <cuda_fp16.h>
#include <cstdint>

#define N_NODES 50000
#define N_EDGES 800000

// ---------------- fp16 scratch (halfs), device-code references only -------
#define HB_X    0L                      // 50000*128
#define HB_H0   6400000L                // 50000*128
#define HB_H1   12800000L               // 50000*256
#define HB_H2   25600000L               // 50000*256
#define HB_AGG  38400000L               // 50000*256
#define HW_PRE  51200000L               // [128][128]
#define HW_1L   51216384L               // [256][128] (transposed: [N][K])
#define HW_1R   51249152L
#define HW_2L   51281920L               // [256][256]
#define HW_2R   51347456L
#define HW_3L   51412992L
#define HW_3R   51478528L
#define HB_TMP  51544064L               // 50000*256 r-path partial
__device__ __align__(16) __half g_half[HB_TMP + 12800000L];   // ~129 MB

__device__ int g_deg[N_NODES];
__device__ int g_rowptr[N_NODES + 1];
__device__ int g_cursor[N_NODES];
__device__ int g_srcs[N_EDGES];
__device__ int g_bsum[256];

// ------------------------------- CSR build --------------------------------
__global__ void k_zero_deg() {
    int i = blockIdx.x * blockDim.x + threadIdx.x;
    if (i < N_NODES) g_deg[i] = 0;
}
__global__ void k_count(const int* __restrict__ ei) {
    int e = blockIdx.x * blockDim.x + threadIdx.x;
    if (e < N_EDGES) {
        int d = ei[N_EDGES + e];
        if (d >= 0 && d < N_NODES) atomicAdd(&g_deg[d], 1);
    }
}
__global__ void k_blockscan() {
    __shared__ int buf[256];
    int tid = threadIdx.x;
    int i = blockIdx.x * 256 + tid;
    int v = (i < N_NODES) ? g_deg[i] : 0;
    buf[tid] = v;
    __syncthreads();
#pragma unroll
    for (int off = 1; off < 256; off <<= 1) {
        int t = (tid >= off) ? buf[tid - off] : 0;
        __syncthreads();
        buf[tid] += t;
        __syncthreads();
    }
    if (i < N_NODES) g_rowptr[i + 1] = buf[tid];
    if (tid == 255) g_bsum[blockIdx.x] = buf[255];
}
__global__ void k_scanblocks(int nblocks) {
    __shared__ int buf[256];
    int tid = threadIdx.x;
    int v = (tid < nblocks) ? g_bsum[tid] : 0;
    buf[tid] = v;
    __syncthreads();
#pragma unroll
    for (int off = 1; off < 256; off <<= 1) {
        int t = (tid >= off) ? buf[tid - off] : 0;
        __syncthreads();
        buf[tid] += t;
        __syncthreads();
    }
    g_bsum[tid] = buf[tid] - v;
}
__global__ void k_add() {
    int tid = threadIdx.x;
    int i = blockIdx.x * 256 + tid;
    if (i < N_NODES) {
        int r = g_rowptr[i + 1] + g_bsum[blockIdx.x];
        g_rowptr[i + 1] = r;
        g_cursor[i] = r - g_deg[i];
        if (i == 0) g_rowptr[0] = 0;
    }
}
__global__ void k_scatter(const int* __restrict__ ei) {
    int e = blockIdx.x * blockDim.x + threadIdx.x;
    if (e < N_EDGES) {
        int d = ei[N_EDGES + e];
        int s = ei[e];
        if (d >= 0 && d < N_NODES) {
            int p = atomicAdd(&g_cursor[d], 1);
            g_srcs[p] = (s >= 0 && s < N_NODES) ? s : 0;
        }
    }
}

// ------------------ fp16 conversion: x + transposed weights ---------------
__global__ void k_half_x(const float* __restrict__ x) {
    int i = blockIdx.x * blockDim.x + threadIdx.x;
    if (i < N_NODES * 128 / 4) {
        float4 v = ((const float4*)x)[i];
        __half2 h0 = __floats2half2_rn(v.x, v.y);
        __half2 h1 = __floats2half2_rn(v.z, v.w);
        uint2 u = make_uint2(*(uint32_t*)&h0, *(uint32_t*)&h1);
        ((uint2*)(g_half + HB_X))[i] = u;
    }
}

struct WTJob { const float* W; long out; int K, N; };
struct WTArgs { WTJob j[7]; };
__global__ void k_wt(WTArgs a) {
    WTJob jb = a.j[blockIdx.z];
    __shared__ float tsm[32][33];
    int tx = threadIdx.x, ty = threadIdx.y;               // 32 x 8
    int n0 = blockIdx.x * 32, k0 = blockIdx.y * 32;
    if (n0 >= jb.N || k0 >= jb.K) return;
#pragma unroll
    for (int i = 0; i < 4; ++i)
        tsm[ty + 8 * i][tx] = jb.W[(size_t)(k0 + ty + 8 * i) * jb.N + n0 + tx];
    __syncthreads();
#pragma unroll
    for (int i = 0; i < 4; ++i)
        g_half[jb.out + (size_t)(n0 + ty + 8 * i) * jb.K + k0 + tx] =
            __float2half_rn(tsm[tx][ty + 8 * i]);
}

// --------------------------- mean aggregation (fp16) ----------------------
template <int D>
__global__ void k_agg(long in_off) {
    const __half* __restrict__ h = g_half + in_off;
    __half* __restrict__ out     = g_half + HB_AGG;
    int w    = (blockIdx.x * blockDim.x + threadIdx.x) >> 5;
    int lane = threadIdx.x & 31;
    if (w >= N_NODES) return;
    int s0 = g_rowptr[w];
    int s1 = g_rowptr[w + 1];
    constexpr int PL = D / 32;
    float a[PL];
#pragma unroll
    for (int i = 0; i < PL; ++i) a[i] = 0.f;

    auto accum = [&](int src) {
        const __half* row = h + (size_t)src * D;
        if (D == 256) {
            uint4 u = ((const uint4*)row)[lane];
            float2 f0 = __half22float2(*(__half2*)&u.x);
            float2 f1 = __half22float2(*(__half2*)&u.y);
            float2 f2 = __half22float2(*(__half2*)&u.z);
            float2 f3 = __half22float2(*(__half2*)&u.w);
            a[0] += f0.x; a[1] += f0.y; a[2] += f1.x; a[3] += f1.y;
            a[4] += f2.x; a[5] += f2.y; a[6] += f3.x; a[7] += f3.y;
        } else {
            uint2 u = ((const uint2*)row)[lane];
            float2 f0 = __half22float2(*(__half2*)&u.x);
            float2 f1 = __half22float2(*(__half2*)&u.y);
            a[0] += f0.x; a[1] += f0.y; a[2] += f1.x; a[3] += f1.y;
        }
    };

    int e = s0;
    for (; e + 1 < s1; e += 2) {
        int i0 = g_srcs[e], i1 = g_srcs[e + 1];
        accum(i0);
        accum(i1);
    }
    if (e < s1) accum(g_srcs[e]);

    float inv = 1.0f / (float)max(s1 - s0, 1);
    __half* o = out + (size_t)w * D + lane * PL;
    if (D == 256) {
        __half2 h0 = __floats2half2_rn(a[0] * inv, a[1] * inv);
        __half2 h1 = __floats2half2_rn(a[2] * inv, a[3] * inv);
        __half2 h2 = __floats2half2_rn(a[4] * inv, a[5] * inv);
        __half2 h3 = __floats2half2_rn(a[6] * inv, a[7] * inv);
        uint4 u = make_uint4(*(uint32_t*)&h0, *(uint32_t*)&h1,
                             *(uint32_t*)&h2, *(uint32_t*)&h3);
        *(uint4*)o = u;
    } else {
        __half2 h0 = __floats2half2_rn(a[0] * inv, a[1] * inv);
        __half2 h1 = __floats2half2_rn(a[2] * inv, a[3] * inv);
        uint2 u = make_uint2(*(uint32_t*)&h0, *(uint32_t*)&h1);
        *(uint2*)o = u;
    }
}

// ------------------------- fp16 tensor-core GEMM --------------------------
// C = A@W^T (+bias) (+add) (+relu).  W stored [N][K] fp16.
// BM=BN=128, BK=32, 2-stage cp.async, 8 warps, 64x32 warp tile of m16n8k16.
#define AT_HALFS 5120                      // 128*40
#define AT_BYTES 10240
#define GEMM_SMEM_BYTES (4 * AT_BYTES)     // 40960

__device__ __forceinline__ void mma_f16(float* c, const uint32_t* a, const uint32_t* b) {
    asm volatile(
        "mma.sync.aligned.m16n8k16.row.col.f32.f16.f16.f32 "
        "{%0,%1,%2,%3}, {%4,%5,%6,%7}, {%8,%9}, {%0,%1,%2,%3};"
        : "+f"(c[0]), "+f"(c[1]), "+f"(c[2]), "+f"(c[3])
        : "r"(a[0]), "r"(a[1]), "r"(a[2]), "r"(a[3]), "r"(b[0]), "r"(b[1]));
}
__device__ __forceinline__ void cpa16(uint32_t dst, const void* src, int bytes) {
    asm volatile("cp.async.cg.shared.global [%0], [%1], 16, %2;"
                 :: "r"(dst), "l"(src), "r"(bytes));
}

__global__ void __launch_bounds__(256)
k_gemm_f16(long a_off, long w_off,
           const float* __restrict__ bias, int use_bias,
           long add_off,
           float* __restrict__ extC, long ho_off,
           int M, int K, int Nout, int relu) {
    const __half* A = g_half + a_off;
    const __half* W = g_half + w_off;

    extern __shared__ __half hsm[];
    uint32_t smem_u32 = (uint32_t)__cvta_generic_to_shared(hsm);

    int t    = threadIdx.x;
    int wid  = t >> 5, lane = t & 31;
    int gid  = lane >> 2, tig = lane & 3;
    int wm   = (wid >> 2) * 64;
    int wn   = (wid & 3) * 32;
    int row0 = blockIdx.y * 128;
    int n0   = blockIdx.x * 128;

    int KT = K >> 5;

    float acc[4][4][4];
#pragma unroll
    for (int i = 0; i < 4; ++i)
#pragma unroll
        for (int j = 0; j < 4; ++j)
#pragma unroll
            for (int r = 0; r < 4; ++r) acc[i][j][r] = 0.f;

    auto issue = [&](int it, int st) {
        int k0 = it << 5;
#pragma unroll
        for (int p = 0; p < 2; ++p) {
            int idx = t + 256 * p;
            int m = idx >> 2, ch = idx & 3;
            bool v = (row0 + m) < M;
            const __half* src = A + (size_t)(v ? row0 + m : 0) * K + k0 + ch * 8;
            uint32_t dst = smem_u32 + (uint32_t)(st * AT_BYTES + m * 80 + ch * 16);
            cpa16(dst, src, v ? 16 : 0);
        }
#pragma unroll
        for (int p = 0; p < 2; ++p) {
            int idx = t + 256 * p;
            int n = idx >> 2, ch = idx & 3;
            const __half* src = W + (size_t)(n0 + n) * K + k0 + ch * 8;
            uint32_t dst = smem_u32 + (uint32_t)(2 * AT_BYTES + st * AT_BYTES + n * 80 + ch * 16);
            cpa16(dst, src, 16);
        }
        asm volatile("cp.async.commit_group;");
    };

    issue(0, 0);
    for (int it = 0; it < KT; ++it) {
        if (it + 1 < KT) {
            issue(it + 1, (it + 1) & 1);
            asm volatile("cp.async.wait_group 1;");
        } else {
            asm volatile("cp.async.wait_group 0;");
        }
        __syncthreads();
        const __half* Asp = hsm + (it & 1) * AT_HALFS;
        const __half* Bsp = hsm + 2 * AT_HALFS + (it & 1) * AT_HALFS;
#pragma unroll
        for (int ks = 0; ks < 2; ++ks) {
            int kk = ks * 16;
            uint32_t af[4][4], bf[4][2];
#pragma unroll
            for (int i = 0; i < 4; ++i) {
                int mb = wm + i * 16;
                af[i][0] = *(const uint32_t*)(Asp + (mb + gid) * 40 + kk + 2 * tig);
                af[i][1] = *(const uint32_t*)(Asp + (mb + gid + 8) * 40 + kk + 2 * tig);
                af[i][2] = *(const uint32_t*)(Asp + (mb + gid) * 40 + kk + 8 + 2 * tig);
                af[i][3] = *(const uint32_t*)(Asp + (mb + gid + 8) * 40 + kk + 8 + 2 * tig);
            }
#pragma unroll
            for (int j = 0; j < 4; ++j) {
                int nb = wn + j * 8;
                bf[j][0] = *(const uint32_t*)(Bsp + (nb + gid) * 40 + kk + 2 * tig);
                bf[j][1] = *(const uint32_t*)(Bsp + (nb + gid) * 40 + kk + 8 + 2 * tig);
            }
#pragma unroll
            for (int i = 0; i < 4; ++i)
#pragma unroll
                for (int j = 0; j < 4; ++j) mma_f16(acc[i][j], af[i], bf[j]);
        }
        __syncthreads();
    }

    // ---- epilogue: (+bias) (+fp16 add) (+relu); fp16 OR fp32 store ----
    const __half* Tp = g_half + ((add_off >= 0) ? add_off : 0);
#pragma unroll
    for (int j = 0; j < 4; ++j) {
        int cb = n0 + wn + j * 8 + 2 * tig;
        float bv0 = use_bias ? bias[cb]     : 0.f;
        float bv1 = use_bias ? bias[cb + 1] : 0.f;
#pragma unroll
        for (int i = 0; i < 4; ++i) {
            int rb = row0 + wm + i * 16 + gid;
#pragma unroll
            for (int h = 0; h < 2; ++h) {
                int r = rb + 8 * h;
                if (r >= M) continue;
                float v0 = acc[i][j][2 * h]     + bv0;
                float v1 = acc[i][j][2 * h + 1] + bv1;
                if (add_off >= 0) {
                    float2 tv = __half22float2(
                        *(const __half2*)(Tp + (size_t)r * Nout + cb));
                    v0 += tv.x; v1 += tv.y;
                }
                if (relu) { v0 = fmaxf(v0, 0.f); v1 = fmaxf(v1, 0.f); }
                if (ho_off >= 0)
                    *(__half2*)(g_half + ho_off + (size_t)r * Nout + cb) =
                        __floats2half2_rn(v0, v1);
                else
                    *(float2*)(extC + (size_t)r * Nout + cb) = make_float2(v0, v1);
            }
        }
    }
}

// ------------------------------ normalize ---------------------------------
__global__ void k_norm(float* __restrict__ y) {
    int w    = (blockIdx.x * blockDim.x + threadIdx.x) >> 5;
    int lane = threadIdx.x & 31;
    if (w >= N_NODES) return;
    float4* r = (float4*)(y + (size_t)w * 256);
    float4 v0 = r[lane];
    float4 v1 = r[lane + 32];
    float ss = v0.x * v0.x + v0.y * v0.y + v0.z * v0.z + v0.w * v0.w +
               v1.x * v1.x + v1.y * v1.y + v1.z * v1.z + v1.w * v1.w;
#pragma unroll
    for (int o = 16; o > 0; o >>= 1) ss += __shfl_xor_sync(0xffffffffu, ss, o);
    float inv = 1.0f / fmaxf(sqrtf(ss), 1e-12f);
    v0.x *= inv; v0.y *= inv; v0.z *= inv; v0.w *= inv;
    v1.x *= inv; v1.y *= inv; v1.z *= inv; v1.w *= inv;
    r[lane]      = v0;
    r[lane + 32] = v1;
}

// -------------------------------- launch ----------------------------------
extern "C" void kernel_launch(void* const* d_in, const int* in_sizes, int n_in,
                              void* d_out, int out_size) {
    const float* x     = (const float*)d_in[0];
    const int*   ei    = (const int*)d_in[1];
    const float* pre_W = (const float*)d_in[2];
    const float* pre_b = (const float*)d_in[3];
    const float* W1l   = (const float*)d_in[4];
    const float* b1    = (const float*)d_in[5];
    const float* W1r   = (const float*)d_in[6];
    const float* W2l   = (const float*)d_in[7];
    const float* b2    = (const float*)d_in[8];
    const float* W2r   = (const float*)d_in[9];
    const float* W3l   = (const float*)d_in[10];
    const float* b3    = (const float*)d_in[11];
    const float* W3r   = (const float*)d_in[12];
    float*       out   = (float*)d_out;

    static cudaStream_t s_b = nullptr;
    static cudaEvent_t  ev[8] = {};
    if (!s_b) {
        cudaFuncSetAttribute(k_gemm_f16, cudaFuncAttributeMaxDynamicSharedMemorySize,
                             GEMM_SMEM_BYTES);
        cudaStreamCreateWithFlags(&s_b, cudaStreamNonBlocking);
        for (int i = 0; i < 8; ++i)
            cudaEventCreateWithFlags(&ev[i], cudaEventDisableTiming);
    }

    const int NB = (N_NODES + 255) / 256;
    dim3 g1(1, (N_NODES + 127) / 128);
    dim3 g2(2, (N_NODES + 127) / 128);
    const int AGG_BLOCKS = (N_NODES + 7) / 8;

    // ---- fork: CSR build on side stream (overlap convert + pre-GEMM)
    cudaEventRecord(ev[0], 0);
    cudaStreamWaitEvent(s_b, ev[0], 0);
    k_zero_deg<<<NB, 256, 0, s_b>>>();
    k_count<<<(N_EDGES + 255) / 256, 256, 0, s_b>>>(ei);
    k_blockscan<<<NB, 256, 0, s_b>>>();
    k_scanblocks<<<1, 256, 0, s_b>>>(NB);
    k_add<<<NB, 256, 0, s_b>>>();
    k_scatter<<<(N_EDGES + 255) / 256, 256, 0, s_b>>>(ei);
    cudaEventRecord(ev[1], s_b);          // CSR done

    // ---- main: fp16 conversions + pre-GEMM -> h0
    k_half_x<<<(N_NODES * 32 + 255) / 256, 256>>>(x);
    WTArgs wa;
    wa.j[0] = { pre_W, HW_PRE, 128, 128 };
    wa.j[1] = { W1l,   HW_1L,  128, 256 };
    wa.j[2] = { W1r,   HW_1R,  128, 256 };
    wa.j[3] = { W2l,   HW_2L,  256, 256 };
    wa.j[4] = { W2r,   HW_2R,  256, 256 };
    wa.j[5] = { W3l,   HW_3L,  256, 256 };
    wa.j[6] = { W3r,   HW_3R,  256, 256 };
    k_wt<<<dim3(8, 8, 7), dim3(32, 8)>>>(wa);

    k_gemm_f16<<<g1, 256, GEMM_SMEM_BYTES>>>(HB_X, HW_PRE, pre_b, 1, -1L,
                                             nullptr, HB_H0, N_NODES, 128, 128, 0);
    cudaEventRecord(ev[2], 0);            // h0 ready

    // ===== layer 1: r-GEMM (s_b) || agg (main), then l-GEMM =====
    cudaStreamWaitEvent(s_b, ev[2], 0);
    k_gemm_f16<<<g2, 256, GEMM_SMEM_BYTES, s_b>>>(HB_H0, HW_1R, b1, 1, -1L,
                                                  nullptr, HB_TMP, N_NODES, 128, 256, 0);
    cudaEventRecord(ev[3], s_b);          // tmp1 ready

    cudaStreamWaitEvent(0, ev[1], 0);     // CSR before first gather
    k_agg<128><<<AGG_BLOCKS, 256>>>(HB_H0);
    cudaStreamWaitEvent(0, ev[3], 0);
    k_gemm_f16<<<g2, 256, GEMM_SMEM_BYTES>>>(HB_AGG, HW_1L, nullptr, 0, HB_TMP,
                                             nullptr, HB_H1, N_NODES, 128, 256, 1);
    cudaEventRecord(ev[4], 0);            // h1 ready

    // ===== layer 2 =====
    cudaStreamWaitEvent(s_b, ev[4], 0);
    k_gemm_f16<<<g2, 256, GEMM_SMEM_BYTES, s_b>>>(HB_H1, HW_2R, b2, 1, -1L,
                                                  nullptr, HB_TMP, N_NODES, 256, 256, 0);
    cudaEventRecord(ev[5], s_b);

    k_agg<256><<<AGG_BLOCKS, 256>>>(HB_H1);
    cudaStreamWaitEvent(0, ev[5], 0);
    k_gemm_f16<<<g2, 256, GEMM_SMEM_BYTES>>>(HB_AGG, HW_2L, nullptr, 0, HB_TMP,
                                             nullptr, HB_H2, N_NODES, 256, 256, 1);
    cudaEventRecord(ev[6], 0);            // h2 ready

    // ===== layer 3 (no relu) -> fp32 out =====
    cudaStreamWaitEvent(s_b, ev[6], 0);
    k_gemm_f16<<<g2, 256, GEMM_SMEM_BYTES, s_b>>>(HB_H2, HW_3R, b3, 1, -1L,
                                                  nullptr, HB_TMP, N_NODES, 256, 256, 0);
    cudaEventRecord(ev[7], s_b);

    k_agg<256><<<AGG_BLOCKS, 256>>>(HB_H2);
    cudaStreamWaitEvent(0, ev[7], 0);
    k_gemm_f16<<<g2, 256, GEMM_SMEM_BYTES>>>(HB_AGG, HW_3L, nullptr, 0, HB_TMP,
                                             out, -1L, N_NODES, 256, 256, 0);

    // L2 normalize rows in place
    k_norm<<<AGG_BLOCKS, 256>>>(out);
}

// round 12
// speedup vs baseline: 1.2531x; 1.2531x over previous
#include <cuda_runtime.h>
#include <cuda_fp16.h>
#include <cstdint>

#define N_NODES 50000
#define N_EDGES 800000

// ---------------- fp16 scratch (halfs), device-code references only -------
#define HB_X    0L                      // 50000*128
#define HB_H0   6400000L                // 50000*128
#define HB_H1   12800000L               // 50000*256
#define HB_H2   25600000L               // 50000*256
#define HB_AGG  38400000L               // 50000*256
#define HW_PRE  51200000L               // [128][128]
#define HW_1L   51216384L               // [256][128] (transposed: [N][K])
#define HW_1R   51249152L
#define HW_2L   51281920L               // [256][256]
#define HW_2R   51347456L
#define HW_3L   51412992L
#define HW_3R   51478528L
__device__ __align__(16) __half g_half[51544064L];   // ~103 MB

__device__ int g_deg[N_NODES];
__device__ int g_rowptr[N_NODES + 1];
__device__ int g_cursor[N_NODES];
__device__ int g_srcs[N_EDGES];
__device__ int g_bsum[256];

// ------------------------------- CSR build --------------------------------
__global__ void k_zero_deg() {
    int i = blockIdx.x * blockDim.x + threadIdx.x;
    if (i < N_NODES) g_deg[i] = 0;
}
__global__ void k_count(const int* __restrict__ ei) {
    int e = blockIdx.x * blockDim.x + threadIdx.x;
    if (e < N_EDGES) {
        int d = ei[N_EDGES + e];
        if (d >= 0 && d < N_NODES) atomicAdd(&g_deg[d], 1);
    }
}
__global__ void k_blockscan() {
    __shared__ int buf[256];
    int tid = threadIdx.x;
    int i = blockIdx.x * 256 + tid;
    int v = (i < N_NODES) ? g_deg[i] : 0;
    buf[tid] = v;
    __syncthreads();
#pragma unroll
    for (int off = 1; off < 256; off <<= 1) {
        int t = (tid >= off) ? buf[tid - off] : 0;
        __syncthreads();
        buf[tid] += t;
        __syncthreads();
    }
    if (i < N_NODES) g_rowptr[i + 1] = buf[tid];
    if (tid == 255) g_bsum[blockIdx.x] = buf[255];
}
__global__ void k_scanblocks(int nblocks) {
    __shared__ int buf[256];
    int tid = threadIdx.x;
    int v = (tid < nblocks) ? g_bsum[tid] : 0;
    buf[tid] = v;
    __syncthreads();
#pragma unroll
    for (int off = 1; off < 256; off <<= 1) {
        int t = (tid >= off) ? buf[tid - off] : 0;
        __syncthreads();
        buf[tid] += t;
        __syncthreads();
    }
    g_bsum[tid] = buf[tid] - v;
}
__global__ void k_add() {
    int tid = threadIdx.x;
    int i = blockIdx.x * 256 + tid;
    if (i < N_NODES) {
        int r = g_rowptr[i + 1] + g_bsum[blockIdx.x];
        g_rowptr[i + 1] = r;
        g_cursor[i] = r - g_deg[i];
        if (i == 0) g_rowptr[0] = 0;
    }
}
__global__ void k_scatter(const int* __restrict__ ei) {
    int e = blockIdx.x * blockDim.x + threadIdx.x;
    if (e < N_EDGES) {
        int d = ei[N_EDGES + e];
        int s = ei[e];
        if (d >= 0 && d < N_NODES) {
            int p = atomicAdd(&g_cursor[d], 1);
            g_srcs[p] = (s >= 0 && s < N_NODES) ? s : 0;
        }
    }
}

// ------------------ fp16 conversion: x + transposed weights ---------------
__global__ void k_half_x(const float* __restrict__ x) {
    int i = blockIdx.x * blockDim.x + threadIdx.x;
    if (i < N_NODES * 128 / 4) {
        float4 v = ((const float4*)x)[i];
        __half2 h0 = __floats2half2_rn(v.x, v.y);
        __half2 h1 = __floats2half2_rn(v.z, v.w);
        uint2 u = make_uint2(*(uint32_t*)&h0, *(uint32_t*)&h1);
        ((uint2*)(g_half + HB_X))[i] = u;
    }
}

struct WTJob { const float* W; long out; int K, N; };
struct WTArgs { WTJob j[7]; };
__global__ void k_wt(WTArgs a) {
    WTJob jb = a.j[blockIdx.z];
    __shared__ float tsm[32][33];
    int tx = threadIdx.x, ty = threadIdx.y;               // 32 x 8
    int n0 = blockIdx.x * 32, k0 = blockIdx.y * 32;
    if (n0 >= jb.N || k0 >= jb.K) return;
#pragma unroll
    for (int i = 0; i < 4; ++i)
        tsm[ty + 8 * i][tx] = jb.W[(size_t)(k0 + ty + 8 * i) * jb.N + n0 + tx];
    __syncthreads();
#pragma unroll
    for (int i = 0; i < 4; ++i)
        g_half[jb.out + (size_t)(n0 + ty + 8 * i) * jb.K + k0 + tx] =
            __float2half_rn(tsm[tx][ty + 8 * i]);
}

// --------------------------- mean aggregation (fp16) ----------------------
template <int D>
__global__ void k_agg(long in_off) {
    const __half* __restrict__ h = g_half + in_off;
    __half* __restrict__ out     = g_half + HB_AGG;
    int w    = (blockIdx.x * blockDim.x + threadIdx.x) >> 5;
    int lane = threadIdx.x & 31;
    if (w >= N_NODES) return;
    int s0 = g_rowptr[w];
    int s1 = g_rowptr[w + 1];
    constexpr int PL = D / 32;
    float a[PL];
#pragma unroll
    for (int i = 0; i < PL; ++i) a[i] = 0.f;

    auto accum = [&](int src) {
        const __half* row = h + (size_t)src * D;
        if (D == 256) {
            uint4 u = ((const uint4*)row)[lane];
            float2 f0 = __half22float2(*(__half2*)&u.x);
            float2 f1 = __half22float2(*(__half2*)&u.y);
            float2 f2 = __half22float2(*(__half2*)&u.z);
            float2 f3 = __half22float2(*(__half2*)&u.w);
            a[0] += f0.x; a[1] += f0.y; a[2] += f1.x; a[3] += f1.y;
            a[4] += f2.x; a[5] += f2.y; a[6] += f3.x; a[7] += f3.y;
        } else {
            uint2 u = ((const uint2*)row)[lane];
            float2 f0 = __half22float2(*(__half2*)&u.x);
            float2 f1 = __half22float2(*(__half2*)&u.y);
            a[0] += f0.x; a[1] += f0.y; a[2] += f1.x; a[3] += f1.y;
        }
    };

    int e = s0;
    for (; e + 1 < s1; e += 2) {
        int i0 = g_srcs[e], i1 = g_srcs[e + 1];
        accum(i0);
        accum(i1);
    }
    if (e < s1) accum(g_srcs[e]);

    float inv = 1.0f / (float)max(s1 - s0, 1);
    __half* o = out + (size_t)w * D + lane * PL;
    if (D == 256) {
        __half2 h0 = __floats2half2_rn(a[0] * inv, a[1] * inv);
        __half2 h1 = __floats2half2_rn(a[2] * inv, a[3] * inv);
        __half2 h2 = __floats2half2_rn(a[4] * inv, a[5] * inv);
        __half2 h3 = __floats2half2_rn(a[6] * inv, a[7] * inv);
        uint4 u = make_uint4(*(uint32_t*)&h0, *(uint32_t*)&h1,
                             *(uint32_t*)&h2, *(uint32_t*)&h3);
        *(uint4*)o = u;
    } else {
        __half2 h0 = __floats2half2_rn(a[0] * inv, a[1] * inv);
        __half2 h1 = __floats2half2_rn(a[2] * inv, a[3] * inv);
        uint2 u = make_uint2(*(uint32_t*)&h0, *(uint32_t*)&h1);
        *(uint2*)o = u;
    }
}

// ------------------------- fp16 tensor-core GEMM --------------------------
// C = A1@W1^T (+ A2@W2^T) + bias (+relu). W stored [N][K] fp16.
// BM=BN=128, BK=32, 3-stage cp.async, 8 warps, 64x32 warp tile of m16n8k16.
#define AT_HALFS 5120                      // 128*40
#define AT_BYTES 10240
#define NSTAGE   3
#define GEMM_SMEM_BYTES (2 * NSTAGE * AT_BYTES)   // 61440

__device__ __forceinline__ void mma_f16(float* c, const uint32_t* a, const uint32_t* b) {
    asm volatile(
        "mma.sync.aligned.m16n8k16.row.col.f32.f16.f16.f32 "
        "{%0,%1,%2,%3}, {%4,%5,%6,%7}, {%8,%9}, {%0,%1,%2,%3};"
        : "+f"(c[0]), "+f"(c[1]), "+f"(c[2]), "+f"(c[3])
        : "r"(a[0]), "r"(a[1]), "r"(a[2]), "r"(a[3]), "r"(b[0]), "r"(b[1]));
}
__device__ __forceinline__ void cpa16(uint32_t dst, const void* src, int bytes) {
    asm volatile("cp.async.cg.shared.global [%0], [%1], 16, %2;"
                 :: "r"(dst), "l"(src), "r"(bytes));
}

__global__ void __launch_bounds__(256, 2)
k_gemm_f16(long a1_off, int dual, long a2_off,
           long w1_off, long w2_off,
           const float* __restrict__ bias,
           float* __restrict__ extC, long ho_off,
           int M, int K, int Nout, int relu) {
    const __half* A1 = g_half + a1_off;
    const __half* A2 = g_half + a2_off;
    const __half* W1 = g_half + w1_off;
    const __half* W2 = g_half + w2_off;

    extern __shared__ __half hsm[];
    uint32_t smem_u32 = (uint32_t)__cvta_generic_to_shared(hsm);

    int t    = threadIdx.x;
    int wid  = t >> 5, lane = t & 31;
    int gid  = lane >> 2, tig = lane & 3;
    int wm   = (wid >> 2) * 64;
    int wn   = (wid & 3) * 32;
    int row0 = blockIdx.y * 128;
    int n0   = blockIdx.x * 128;

    int kblocks = K >> 5;
    int KT = (dual ? 2 : 1) * kblocks;

    float acc[4][4][4];
#pragma unroll
    for (int i = 0; i < 4; ++i)
#pragma unroll
        for (int j = 0; j < 4; ++j)
#pragma unroll
            for (int r = 0; r < 4; ++r) acc[i][j][r] = 0.f;

    auto issue = [&](int it, int st) {
        int ph = it / kblocks;
        int k0 = (it - ph * kblocks) << 5;
        const __half* A = ph ? A2 : A1;
        const __half* W = ph ? W2 : W1;
#pragma unroll
        for (int p = 0; p < 2; ++p) {
            int idx = t + 256 * p;
            int m = idx >> 2, ch = idx & 3;
            bool v = (row0 + m) < M;
            const __half* src = A + (size_t)(v ? row0 + m : 0) * K + k0 + ch * 8;
            uint32_t dst = smem_u32 + (uint32_t)(st * AT_BYTES + m * 80 + ch * 16);
            cpa16(dst, src, v ? 16 : 0);
        }
#pragma unroll
        for (int p = 0; p < 2; ++p) {
            int idx = t + 256 * p;
            int n = idx >> 2, ch = idx & 3;
            const __half* src = W + (size_t)(n0 + n) * K + k0 + ch * 8;
            uint32_t dst = smem_u32 + (uint32_t)(NSTAGE * AT_BYTES + st * AT_BYTES + n * 80 + ch * 16);
            cpa16(dst, src, 16);
        }
        asm volatile("cp.async.commit_group;");
    };

    issue(0, 0);
    if (KT > 1) issue(1, 1);
    for (int it = 0; it < KT; ++it) {
        if (it + 2 < KT) {
            issue(it + 2, (it + 2) % NSTAGE);
            asm volatile("cp.async.wait_group 2;");
        } else if (it + 1 < KT) {
            asm volatile("cp.async.wait_group 1;");
        } else {
            asm volatile("cp.async.wait_group 0;");
        }
        __syncthreads();
        int st = it % NSTAGE;
        const __half* Asp = hsm + st * AT_HALFS;
        const __half* Bsp = hsm + NSTAGE * AT_HALFS + st * AT_HALFS;
#pragma unroll
        for (int ks = 0; ks < 2; ++ks) {
            int kk = ks * 16;
            uint32_t af[4][4], bf[4][2];
#pragma unroll
            for (int i = 0; i < 4; ++i) {
                int mb = wm + i * 16;
                af[i][0] = *(const uint32_t*)(Asp + (mb + gid) * 40 + kk + 2 * tig);
                af[i][1] = *(const uint32_t*)(Asp + (mb + gid + 8) * 40 + kk + 2 * tig);
                af[i][2] = *(const uint32_t*)(Asp + (mb + gid) * 40 + kk + 8 + 2 * tig);
                af[i][3] = *(const uint32_t*)(Asp + (mb + gid + 8) * 40 + kk + 8 + 2 * tig);
            }
#pragma unroll
            for (int j = 0; j < 4; ++j) {
                int nb = wn + j * 8;
                bf[j][0] = *(const uint32_t*)(Bsp + (nb + gid) * 40 + kk + 2 * tig);
                bf[j][1] = *(const uint32_t*)(Bsp + (nb + gid) * 40 + kk + 8 + 2 * tig);
            }
#pragma unroll
            for (int i = 0; i < 4; ++i)
#pragma unroll
                for (int j = 0; j < 4; ++j) mma_f16(acc[i][j], af[i], bf[j]);
        }
        __syncthreads();
    }

    // ---- epilogue: bias (+relu); fp16 h store OR fp32 final store ----
#pragma unroll
    for (int j = 0; j < 4; ++j) {
        int cb = n0 + wn + j * 8 + 2 * tig;
        float bv0 = bias[cb], bv1 = bias[cb + 1];
#pragma unroll
        for (int i = 0; i < 4; ++i) {
            int rb = row0 + wm + i * 16 + gid;
#pragma unroll
            for (int h = 0; h < 2; ++h) {
                int r = rb + 8 * h;
                if (r >= M) continue;
                float v0 = acc[i][j][2 * h]     + bv0;
                float v1 = acc[i][j][2 * h + 1] + bv1;
                if (relu) { v0 = fmaxf(v0, 0.f); v1 = fmaxf(v1, 0.f); }
                if (ho_off >= 0)
                    *(__half2*)(g_half + ho_off + (size_t)r * Nout + cb) =
                        __floats2half2_rn(v0, v1);
                else
                    *(float2*)(extC + (size_t)r * Nout + cb) = make_float2(v0, v1);
            }
        }
    }
}

// ------------------------------ normalize ---------------------------------
__global__ void k_norm(float* __restrict__ y) {
    int w    = (blockIdx.x * blockDim.x + threadIdx.x) >> 5;
    int lane = threadIdx.x & 31;
    if (w >= N_NODES) return;
    float4* r = (float4*)(y + (size_t)w * 256);
    float4 v0 = r[lane];
    float4 v1 = r[lane + 32];
    float ss = v0.x * v0.x + v0.y * v0.y + v0.z * v0.z + v0.w * v0.w +
               v1.x * v1.x + v1.y * v1.y + v1.z * v1.z + v1.w * v1.w;
#pragma unroll
    for (int o = 16; o > 0; o >>= 1) ss += __shfl_xor_sync(0xffffffffu, ss, o);
    float inv = 1.0f / fmaxf(sqrtf(ss), 1e-12f);
    v0.x *= inv; v0.y *= inv; v0.z *= inv; v0.w *= inv;
    v1.x *= inv; v1.y *= inv; v1.z *= inv; v1.w *= inv;
    r[lane]      = v0;
    r[lane + 32] = v1;
}

// -------------------------------- launch ----------------------------------
extern "C" void kernel_launch(void* const* d_in, const int* in_sizes, int n_in,
                              void* d_out, int out_size) {
    const float* x     = (const float*)d_in[0];
    const int*   ei    = (const int*)d_in[1];
    const float* pre_W = (const float*)d_in[2];
    const float* pre_b = (const float*)d_in[3];
    const float* W1l   = (const float*)d_in[4];
    const float* b1    = (const float*)d_in[5];
    const float* W1r   = (const float*)d_in[6];
    const float* W2l   = (const float*)d_in[7];
    const float* b2    = (const float*)d_in[8];
    const float* W2r   = (const float*)d_in[9];
    const float* W3l   = (const float*)d_in[10];
    const float* b3    = (const float*)d_in[11];
    const float* W3r   = (const float*)d_in[12];
    float*       out   = (float*)d_out;

    static cudaStream_t s_csr = nullptr;
    static cudaEvent_t  s_ev0 = nullptr, s_ev1 = nullptr;
    if (!s_csr) {
        cudaFuncSetAttribute(k_gemm_f16, cudaFuncAttributeMaxDynamicSharedMemorySize,
                             GEMM_SMEM_BYTES);
        cudaStreamCreateWithFlags(&s_csr, cudaStreamNonBlocking);
        cudaEventCreateWithFlags(&s_ev0, cudaEventDisableTiming);
        cudaEventCreateWithFlags(&s_ev1, cudaEventDisableTiming);
    }

    const int NB = (N_NODES + 255) / 256;

    // ---- fork: CSR build on side stream
    cudaEventRecord(s_ev0, 0);
    cudaStreamWaitEvent(s_csr, s_ev0, 0);
    k_zero_deg<<<NB, 256, 0, s_csr>>>();
    k_count<<<(N_EDGES + 255) / 256, 256, 0, s_csr>>>(ei);
    k_blockscan<<<NB, 256, 0, s_csr>>>();
    k_scanblocks<<<1, 256, 0, s_csr>>>(NB);
    k_add<<<NB, 256, 0, s_csr>>>();
    k_scatter<<<(N_EDGES + 255) / 256, 256, 0, s_csr>>>(ei);
    cudaEventRecord(s_ev1, s_csr);

    // ---- main stream: fp16 conversions + pre-GEMM
    k_half_x<<<(N_NODES * 32 + 255) / 256, 256>>>(x);
    WTArgs wa;
    wa.j[0] = { pre_W, HW_PRE, 128, 128 };
    wa.j[1] = { W1l,   HW_1L,  128, 256 };
    wa.j[2] = { W1r,   HW_1R,  128, 256 };
    wa.j[3] = { W2l,   HW_2L,  256, 256 };
    wa.j[4] = { W2r,   HW_2R,  256, 256 };
    wa.j[5] = { W3l,   HW_3L,  256, 256 };
    wa.j[6] = { W3r,   HW_3R,  256, 256 };
    k_wt<<<dim3(8, 8, 7), dim3(32, 8)>>>(wa);

    dim3 g1(1, (N_NODES + 127) / 128);
    dim3 g2(2, (N_NODES + 127) / 128);
    const int AGG_BLOCKS = (N_NODES + 7) / 8;

    // pre: h0 = x @ pre_W + pre_b  -> fp16 h0
    k_gemm_f16<<<g1, 256, GEMM_SMEM_BYTES>>>(HB_X, 0, 0L, HW_PRE, HW_PRE, pre_b,
                                             nullptr, HB_H0, N_NODES, 128, 128, 0);

    // ---- join: CSR ready before first gather
    cudaStreamWaitEvent(0, s_ev1, 0);

    // layer 1: h1 = relu(mean(h0)@W1l + h0@W1r + b1) -> fp16 h1
    k_agg<128><<<AGG_BLOCKS, 256>>>(HB_H0);
    k_gemm_f16<<<g2, 256, GEMM_SMEM_BYTES>>>(HB_AGG, 1, HB_H0, HW_1L, HW_1R, b1,
                                             nullptr, HB_H1, N_NODES, 128, 256, 1);

    // layer 2 -> fp16 h2
    k_agg<256><<<AGG_BLOCKS, 256>>>(HB_H1);
    k_gemm_f16<<<g2, 256, GEMM_SMEM_BYTES>>>(HB_AGG, 1, HB_H1, HW_2L, HW_2R, b2,
                                             nullptr, HB_H2, N_NODES, 256, 256, 1);

    // layer 3 (no relu) -> fp32 d_out
    k_agg<256><<<AGG_BLOCKS, 256>>>(HB_H2);
    k_gemm_f16<<<g2, 256, GEMM_SMEM_BYTES>>>(HB_AGG, 1, HB_H2, HW_3L, HW_3R, b3,
                                             out, -1L, N_NODES, 256, 256, 0);

    // L2 normalize rows in place
    k_norm<<<AGG_BLOCKS, 256>>>(out);
}